// round 3
// baseline (speedup 1.0000x reference)
#include <cuda_runtime.h>
#include <cuda_bf16.h>

typedef unsigned long long u64;

#define NPTS   65536
#define CCH    64
#define NSMP   16
#define CSW    8
#define EPSV   1e-5f
#define NBW    4   // points (warps) per block in fused kernel

// ---------------- f32x2 helpers ----------------
__device__ __forceinline__ u64 pk2(float a, float b) {
    u64 r; asm("mov.b64 %0, {%1, %2};" : "=l"(r) : "f"(a), "f"(b)); return r;
}
__device__ __forceinline__ void upk2(u64 v, float& a, float& b) {
    asm("mov.b64 {%0, %1}, %2;" : "=f"(a), "=f"(b) : "l"(v));
}
__device__ __forceinline__ u64 ffma2(u64 a, u64 b, u64 c) {
    u64 d; asm("fma.rn.f32x2 %0, %1, %2, %3;" : "=l"(d) : "l"(a), "l"(b), "l"(c)); return d;
}
__device__ __forceinline__ u64 fadd2(u64 a, u64 b) {
    u64 d; asm("add.rn.f32x2 %0, %1, %2;" : "=l"(d) : "l"(a), "l"(b)); return d;
}

// ---------------- scratch tables (L2-resident: 3 x 16MB) ----------------
__device__ float g_xq[NPTS * CCH];
__device__ float g_xk[NPTS * CCH];
__device__ float g_xv[NPTS * CCH];

// =====================================================================
// Kernel 1: xq/xk/xv = x @ W^T + b   ([65536,64] x [64,64], 3 matrices)
// block 128 = (tx 8) x (ty 16); per-thread 4 rows x 8 cols (4 col-pairs).
// Column-pair packed accumulators: b loads directly as u64, only a dup'd.
// =====================================================================
__global__ __launch_bounds__(128) void gemm_qkv(
    const float* __restrict__ x,
    const float* __restrict__ Wq, const float* __restrict__ bq,
    const float* __restrict__ Wk, const float* __restrict__ bk,
    const float* __restrict__ Wv, const float* __restrict__ bv)
{
    __shared__ float sX[64][68];  // sX[k][r] = x[row0+r][k]
    __shared__ float sW[64][68];  // sW[k][j] = W[j][k]
    __shared__ float sB[64];

    const int tid = threadIdx.x;
    const int mat = blockIdx.y;
    const float* W = (mat == 0) ? Wq : (mat == 1) ? Wk : Wv;
    const float* B = (mat == 0) ? bq : (mat == 1) ? bk : bv;
    float* outp    = (mat == 0) ? g_xq : (mat == 1) ? g_xk : g_xv;
    const int row0 = blockIdx.x * 64;

    // transpose-load x tile and W into smem (128 threads)
    const int r  = tid & 63;
    const int kb = (tid >> 6) * 32;   // 0 or 32
    #pragma unroll
    for (int e = 0; e < 8; ++e) {
        float4 vx = *(const float4*)&x[(row0 + r) * 64 + kb + 4 * e];
        sX[kb + 4 * e + 0][r] = vx.x; sX[kb + 4 * e + 1][r] = vx.y;
        sX[kb + 4 * e + 2][r] = vx.z; sX[kb + 4 * e + 3][r] = vx.w;
        float4 vw = *(const float4*)&W[r * 64 + kb + 4 * e];
        sW[kb + 4 * e + 0][r] = vw.x; sW[kb + 4 * e + 1][r] = vw.y;
        sW[kb + 4 * e + 2][r] = vw.z; sW[kb + 4 * e + 3][r] = vw.w;
    }
    if (tid < 64) sB[tid] = B[tid];
    __syncthreads();

    const int tx = tid & 7;    // col group: cols 8*tx..8*tx+7
    const int ty = tid >> 3;   // row group: rows 4*ty..4*ty+3
    const int c0 = 8 * tx;
    const int r0 = 4 * ty;

    u64 acc[4][4];   // [row][colpair]
    #pragma unroll
    for (int cp = 0; cp < 4; ++cp) {
        u64 bp = *(const u64*)&sB[c0 + 2 * cp];
        acc[0][cp] = bp; acc[1][cp] = bp; acc[2][cp] = bp; acc[3][cp] = bp;
    }

    #pragma unroll
    for (int k = 0; k < 64; ++k) {
        ulonglong2 bA = *(const ulonglong2*)&sW[k][c0];       // colpairs 0,1
        ulonglong2 bBv = *(const ulonglong2*)&sW[k][c0 + 4];  // colpairs 2,3
        float4 a4 = *(const float4*)&sX[k][r0];
        u64 a0 = pk2(a4.x, a4.x), a1 = pk2(a4.y, a4.y);
        u64 a2 = pk2(a4.z, a4.z), a3 = pk2(a4.w, a4.w);
        acc[0][0] = ffma2(a0, bA.x, acc[0][0]);
        acc[0][1] = ffma2(a0, bA.y, acc[0][1]);
        acc[0][2] = ffma2(a0, bBv.x, acc[0][2]);
        acc[0][3] = ffma2(a0, bBv.y, acc[0][3]);
        acc[1][0] = ffma2(a1, bA.x, acc[1][0]);
        acc[1][1] = ffma2(a1, bA.y, acc[1][1]);
        acc[1][2] = ffma2(a1, bBv.x, acc[1][2]);
        acc[1][3] = ffma2(a1, bBv.y, acc[1][3]);
        acc[2][0] = ffma2(a2, bA.x, acc[2][0]);
        acc[2][1] = ffma2(a2, bA.y, acc[2][1]);
        acc[2][2] = ffma2(a2, bBv.x, acc[2][2]);
        acc[2][3] = ffma2(a2, bBv.y, acc[2][3]);
        acc[3][0] = ffma2(a3, bA.x, acc[3][0]);
        acc[3][1] = ffma2(a3, bA.y, acc[3][1]);
        acc[3][2] = ffma2(a3, bBv.x, acc[3][2]);
        acc[3][3] = ffma2(a3, bBv.y, acc[3][3]);
    }

    #pragma unroll
    for (int rr = 0; rr < 4; ++rr) {
        float l0, h0, l1, h1, l2, h2, l3, h3;
        upk2(acc[rr][0], l0, h0); upk2(acc[rr][1], l1, h1);
        upk2(acc[rr][2], l2, h2); upk2(acc[rr][3], l3, h3);
        const int row = row0 + r0 + rr;
        *(float4*)&outp[row * 64 + c0]     = make_float4(l0, h0, l1, h1);
        *(float4*)&outp[row * 64 + c0 + 4] = make_float4(l2, h2, l3, h3);
    }
}

// =====================================================================
// Kernel 2: fused point-transformer. One warp per point.
// =====================================================================
__global__ void __launch_bounds__(128, 8) fused_pt(
    const float* __restrict__ p,   const int*   __restrict__ idx,
    const float* __restrict__ Wp1, const float* __restrict__ bp1,
    const float* __restrict__ pg,  const float* __restrict__ pb,
    const float* __restrict__ pm,  const float* __restrict__ pv,
    const float* __restrict__ Wp2, const float* __restrict__ bp2,
    const float* __restrict__ wg1, const float* __restrict__ wb1,
    const float* __restrict__ wm1, const float* __restrict__ wv1,
    const float* __restrict__ Ww1, const float* __restrict__ bw1,
    const float* __restrict__ wg2, const float* __restrict__ wb2,
    const float* __restrict__ wm2, const float* __restrict__ wv2,
    const float* __restrict__ Ww2, const float* __restrict__ bw2,
    float* __restrict__ out)
{
    // block-wide weights
    __shared__ float2 sW1p[32][8];   // {Ww1[o][2cp], Ww1[o][2cp+1]}
    __shared__ float  sW2[8][8];
    __shared__ float  sbw1[8], sa2[8], sb2[8], sbw2[8];
    __shared__ float  sWp1[9], sbp1v[3], spa[3], spbv[3];
    // per-warp (per point)
    __shared__ __align__(16) float  ssw [NBW][16][66];   // w[k][c]
    __shared__ __align__(16) float4 stv4[NBW][16];       // {t0,t1,t2,bits(j)}
    __shared__ __align__(16) float  swl [NBW][16][8];    // logits -> weights

    const int tid = threadIdx.x;

    for (int i = tid; i < 512; i += 128) {
        int cp = i >> 4, rr = i & 15, o = rr >> 1, e = rr & 1;
        ((float*)sW1p)[i] = Ww1[o * 64 + 2 * cp + e];
    }
    if (tid < 64) sW2[tid >> 3][tid & 7] = Ww2[tid];
    if (tid < 8) {
        sbw1[tid] = bw1[tid];
        float a = wg2[tid] * rsqrtf(wv2[tid] + EPSV);
        sa2[tid] = a; sb2[tid] = wb2[tid] - wm2[tid] * a;
        sbw2[tid] = bw2[tid];
    }
    if (tid < 9) sWp1[tid] = Wp1[tid];
    if (tid < 3) {
        sbp1v[tid] = bp1[tid];
        float a = pg[tid] * rsqrtf(pv[tid] + EPSV);
        spa[tid] = a; spbv[tid] = pb[tid] - pm[tid] * a;
    }
    __syncthreads();

    const int w    = tid >> 5;
    const int lane = tid & 31;
    const int n    = blockIdx.x * NBW + w;
    const int c0   = 2 * lane;   // channel pair owned in phases A & C

    // ---- Phase 0: neighbor t values + index, packed per neighbor ----
    if (lane < 16) {
        int j = idx[n * 16 + lane];
        float pnx = p[n * 3 + 0], pny = p[n * 3 + 1], pnz = p[n * 3 + 2];
        float prx = p[j * 3 + 0] - pnx;
        float pry = p[j * 3 + 1] - pny;
        float prz = p[j * 3 + 2] - pnz;
        float u0 = prx * sWp1[0] + pry * sWp1[1] + prz * sWp1[2] + sbp1v[0];
        float u1 = prx * sWp1[3] + pry * sWp1[4] + prz * sWp1[5] + sbp1v[1];
        float u2 = prx * sWp1[6] + pry * sWp1[7] + prz * sWp1[8] + sbp1v[2];
        float t0 = fmaxf(0.f, fmaf(u0, spa[0], spbv[0]));
        float t1 = fmaxf(0.f, fmaf(u1, spa[1], spbv[1]));
        float t2 = fmaxf(0.f, fmaf(u2, spa[2], spbv[2]));
        stv4[w][lane] = make_float4(t0, t1, t2, __int_as_float(j));
    }
    __syncwarp();

    // ---- Phase A: gather xk + relation + pos-enc -> ssw ----
    {
        const u64 xq2  = *(const u64*)&g_xq[n * 64 + c0];
        const u64 wpj0 = pk2(Wp2[c0 * 3 + 0], Wp2[c0 * 3 + 3]);
        const u64 wpj1 = pk2(Wp2[c0 * 3 + 1], Wp2[c0 * 3 + 4]);
        const u64 wpj2 = pk2(Wp2[c0 * 3 + 2], Wp2[c0 * 3 + 5]);
        const u64 bp2d = pk2(bp2[c0], bp2[c0 + 1]);
        float a1_0 = wg1[c0] * rsqrtf(wv1[c0] + EPSV);
        float b1_0 = wb1[c0] - wm1[c0] * a1_0;
        float a1_1 = wg1[c0 + 1] * rsqrtf(wv1[c0 + 1] + EPSV);
        float b1_1 = wb1[c0 + 1] - wm1[c0 + 1] * a1_1;
        const u64 negone = pk2(-1.0f, -1.0f);

        #pragma unroll
        for (int kk = 0; kk < 16; ++kk) {
            float4 tv = stv4[w][kk];                       // 1 LDS.128 bcast
            int j = __float_as_int(tv.w);
            u64 xk2v = *(const u64*)&g_xk[j * 64 + c0];    // coalesced
            u64 pe2  = ffma2(wpj0, pk2(tv.x, tv.x),
                       ffma2(wpj1, pk2(tv.y, tv.y),
                       ffma2(wpj2, pk2(tv.z, tv.z), bp2d)));
            u64 r2   = fadd2(ffma2(xq2, negone, xk2v), pe2);
            float r_0, r_1; upk2(r2, r_0, r_1);
            float w_0 = fmaxf(0.f, fmaf(r_0, a1_0, b1_0));
            float w_1 = fmaxf(0.f, fmaf(r_1, a1_1, b1_1));
            *(u64*)&ssw[w][kk][c0] = pk2(w_0, w_1);
        }
    }
    __syncwarp();

    // ---- Phase B: w @ Ww1^T -> bn2/relu -> Ww2 -> logits ----
    {
        const int k  = lane & 15;
        const int og = lane >> 4;
        u64 pacc[4] = {0ull, 0ull, 0ull, 0ull};
        #pragma unroll
        for (int cp = 0; cp < 32; ++cp) {
            u64 w2 = *(const u64*)&ssw[w][k][2 * cp];
            const ulonglong2* wr = (const ulonglong2*)&sW1p[cp][og * 4];
            ulonglong2 w01 = wr[0], w23 = wr[1];
            pacc[0] = ffma2(w2, w01.x, pacc[0]);
            pacc[1] = ffma2(w2, w01.y, pacc[1]);
            pacc[2] = ffma2(w2, w23.x, pacc[2]);
            pacc[3] = ffma2(w2, w23.y, pacc[3]);
        }
        float hmine[4];
        #pragma unroll
        for (int m = 0; m < 4; ++m) {
            float lo, hi; upk2(pacc[m], lo, hi);
            int o = og * 4 + m;
            float tot = lo + hi + sbw1[o];
            hmine[m] = fmaxf(0.f, fmaf(tot, sa2[o], sb2[o]));
        }
        float hoth[4];
        #pragma unroll
        for (int m = 0; m < 4; ++m)
            hoth[m] = __shfl_xor_sync(0xffffffffu, hmine[m], 16);

        const int omine = og * 4, ooth = omine ^ 4;
        if (og == 0) {
            float lg[8];
            #pragma unroll
            for (int o2 = 0; o2 < 8; ++o2) {
                float l = sbw2[o2];
                #pragma unroll
                for (int m = 0; m < 4; ++m) {
                    l = fmaf(hmine[m], sW2[o2][omine + m], l);
                    l = fmaf(hoth[m],  sW2[o2][ooth  + m], l);
                }
                lg[o2] = l;
            }
            #pragma unroll
            for (int q = 0; q < 4; ++q)
                *(u64*)&swl[w][k][2 * q] = pk2(lg[2 * q], lg[2 * q + 1]);
        }
    }
    __syncwarp();

    // ---- softmax over the 16 neighbors (lanes 0..7, register vals) ----
    if (lane < 8) {
        float vals[16];
        float mx = -1e30f;
        #pragma unroll
        for (int kk = 0; kk < 16; ++kk) { vals[kk] = swl[w][kk][lane]; mx = fmaxf(mx, vals[kk]); }
        float s = 0.f;
        #pragma unroll
        for (int kk = 0; kk < 16; ++kk) { vals[kk] = __expf(vals[kk] - mx); s += vals[kk]; }
        float inv = 1.f / s;
        #pragma unroll
        for (int kk = 0; kk < 16; ++kk) swl[w][kk][lane] = vals[kk] * inv;
    }
    __syncwarp();

    // ---- Phase C: re-gather xv, recompute pe, weighted sum ----
    {
        const u64 wpj0 = pk2(Wp2[c0 * 3 + 0], Wp2[c0 * 3 + 3]);
        const u64 wpj1 = pk2(Wp2[c0 * 3 + 1], Wp2[c0 * 3 + 4]);
        const u64 wpj2 = pk2(Wp2[c0 * 3 + 2], Wp2[c0 * 3 + 5]);
        const u64 bp2d = pk2(bp2[c0], bp2[c0 + 1]);
        const int cs   = c0 & 7;   // even, so pair (cs, cs+1)

        u64 acc = 0ull;
        #pragma unroll
        for (int kk = 0; kk < 16; ++kk) {
            float4 tv = stv4[w][kk];                       // 1 LDS.128 bcast
            int j = __float_as_int(tv.w);
            u64 xv2v = *(const u64*)&g_xv[j * 64 + c0];    // coalesced
            u64 pe2  = ffma2(wpj0, pk2(tv.x, tv.x),
                       ffma2(wpj1, pk2(tv.y, tv.y),
                       ffma2(wpj2, pk2(tv.z, tv.z), bp2d)));
            u64 g2   = *(const u64*)&swl[w][kk][cs];       // weight pair
            acc = ffma2(fadd2(xv2v, pe2), g2, acc);
        }
        float o0, o1; upk2(acc, o0, o1);
        *(float2*)&out[n * 64 + c0] = make_float2(o0, o1);
    }
}

// =====================================================================
extern "C" void kernel_launch(void* const* d_in, const int* in_sizes, int n_in,
                              void* d_out, int out_size)
{
    const float* p   = (const float*)d_in[0];
    const float* x   = (const float*)d_in[1];
    const int*   idx = (const int*)  d_in[2];
    const float* Wq  = (const float*)d_in[3];
    const float* bq  = (const float*)d_in[4];
    const float* Wk  = (const float*)d_in[5];
    const float* bk  = (const float*)d_in[6];
    const float* Wv  = (const float*)d_in[7];
    const float* bv  = (const float*)d_in[8];
    const float* Wp1 = (const float*)d_in[9];
    const float* bp1 = (const float*)d_in[10];
    const float* pg  = (const float*)d_in[11];
    const float* pb  = (const float*)d_in[12];
    const float* pm  = (const float*)d_in[13];
    const float* pv  = (const float*)d_in[14];
    const float* Wp2 = (const float*)d_in[15];
    const float* bp2 = (const float*)d_in[16];
    const float* wg1 = (const float*)d_in[17];
    const float* wb1 = (const float*)d_in[18];
    const float* wm1 = (const float*)d_in[19];
    const float* wv1 = (const float*)d_in[20];
    const float* Ww1 = (const float*)d_in[21];
    const float* bw1 = (const float*)d_in[22];
    const float* wg2 = (const float*)d_in[23];
    const float* wb2 = (const float*)d_in[24];
    const float* wm2 = (const float*)d_in[25];
    const float* wv2 = (const float*)d_in[26];
    const float* Ww2 = (const float*)d_in[27];
    const float* bw2 = (const float*)d_in[28];
    float* out = (float*)d_out;

    gemm_qkv<<<dim3(NPTS / 64, 3, 1), 128>>>(x, Wq, bq, Wk, bk, Wv, bv);
    fused_pt<<<NPTS / NBW, 128>>>(p, idx, Wp1, bp1, pg, pb, pm, pv, Wp2, bp2,
                                  wg1, wb1, wm1, wv1, Ww1, bw1,
                                  wg2, wb2, wm2, wv2, Ww2, bw2, out);
}

// round 4
// speedup vs baseline: 1.1612x; 1.1612x over previous
#include <cuda_runtime.h>
#include <cuda_bf16.h>

typedef unsigned long long u64;

#define NPTS   65536
#define CCH    64
#define NSMP   16
#define CSW    8
#define EPSV   1e-5f
#define NBW    4   // points (warps) per block in fused kernel

// ---------------- f32x2 helpers ----------------
__device__ __forceinline__ u64 pk2(float a, float b) {
    u64 r; asm("mov.b64 %0, {%1, %2};" : "=l"(r) : "f"(a), "f"(b)); return r;
}
__device__ __forceinline__ void upk2(u64 v, float& a, float& b) {
    asm("mov.b64 {%0, %1}, %2;" : "=f"(a), "=f"(b) : "l"(v));
}
__device__ __forceinline__ u64 ffma2(u64 a, u64 b, u64 c) {
    u64 d; asm("fma.rn.f32x2 %0, %1, %2, %3;" : "=l"(d) : "l"(a), "l"(b), "l"(c)); return d;
}
__device__ __forceinline__ u64 fadd2(u64 a, u64 b) {
    u64 d; asm("add.rn.f32x2 %0, %1, %2;" : "=l"(d) : "l"(a), "l"(b)); return d;
}
__device__ __forceinline__ u64 neg2(u64 v) { return v ^ 0x8000000080000000ULL; }

// ---------------- scratch tables (L2-resident: 3 x 16MB) ----------------
__device__ float g_xq[NPTS * CCH];
__device__ float g_xk[NPTS * CCH];
__device__ float g_xv[NPTS * CCH];

// =====================================================================
// Kernel 1: xq/xk/xv = x @ W^T + b  (256-thread version, known good)
// =====================================================================
__global__ __launch_bounds__(256) void gemm_qkv(
    const float* __restrict__ x,
    const float* __restrict__ Wq, const float* __restrict__ bq,
    const float* __restrict__ Wk, const float* __restrict__ bk,
    const float* __restrict__ Wv, const float* __restrict__ bv)
{
    __shared__ float sX[64][68];  // sX[k][r] = x[row0+r][k]
    __shared__ float sW[64][68];  // sW[k][j] = W[j][k]
    __shared__ float sB[64];

    const int tid = threadIdx.x;
    const int mat = blockIdx.y;
    const float* W = (mat == 0) ? Wq : (mat == 1) ? Wk : Wv;
    const float* B = (mat == 0) ? bq : (mat == 1) ? bk : bv;
    float* outp    = (mat == 0) ? g_xq : (mat == 1) ? g_xk : g_xv;
    const int row0 = blockIdx.x * 64;

    const int r  = tid & 63;
    const int kb = (tid >> 6) << 4;
    #pragma unroll
    for (int e = 0; e < 4; ++e) {
        float4 vx = *(const float4*)&x[(row0 + r) * 64 + kb + 4 * e];
        sX[kb + 4 * e + 0][r] = vx.x; sX[kb + 4 * e + 1][r] = vx.y;
        sX[kb + 4 * e + 2][r] = vx.z; sX[kb + 4 * e + 3][r] = vx.w;
        float4 vw = *(const float4*)&W[r * 64 + kb + 4 * e];
        sW[kb + 4 * e + 0][r] = vw.x; sW[kb + 4 * e + 1][r] = vw.y;
        sW[kb + 4 * e + 2][r] = vw.z; sW[kb + 4 * e + 3][r] = vw.w;
    }
    if (tid < 64) sB[tid] = B[tid];
    __syncthreads();

    const int tx = tid & 15;
    const int ty = tid >> 4;

    u64 acc[2][4];
    #pragma unroll
    for (int c = 0; c < 4; ++c) {
        float bb = sB[4 * tx + c];
        u64 bd = pk2(bb, bb);
        acc[0][c] = bd; acc[1][c] = bd;
    }

    #pragma unroll
    for (int k = 0; k < 64; ++k) {
        u64 a0 = *(const u64*)&sX[k][4 * ty];
        u64 a1 = *(const u64*)&sX[k][4 * ty + 2];
        float4 b4 = *(const float4*)&sW[k][4 * tx];
        u64 b0 = pk2(b4.x, b4.x), b1 = pk2(b4.y, b4.y);
        u64 b2 = pk2(b4.z, b4.z), b3 = pk2(b4.w, b4.w);
        acc[0][0] = ffma2(a0, b0, acc[0][0]);  acc[1][0] = ffma2(a1, b0, acc[1][0]);
        acc[0][1] = ffma2(a0, b1, acc[0][1]);  acc[1][1] = ffma2(a1, b1, acc[1][1]);
        acc[0][2] = ffma2(a0, b2, acc[0][2]);  acc[1][2] = ffma2(a1, b2, acc[1][2]);
        acc[0][3] = ffma2(a0, b3, acc[0][3]);  acc[1][3] = ffma2(a1, b3, acc[1][3]);
    }

    #pragma unroll
    for (int rp = 0; rp < 2; ++rp) {
        float lo0, hi0, lo1, hi1, lo2, hi2, lo3, hi3;
        upk2(acc[rp][0], lo0, hi0); upk2(acc[rp][1], lo1, hi1);
        upk2(acc[rp][2], lo2, hi2); upk2(acc[rp][3], lo3, hi3);
        const int row = row0 + 4 * ty + 2 * rp;
        *(float4*)&outp[(row + 0) * 64 + 4 * tx] = make_float4(lo0, lo1, lo2, lo3);
        *(float4*)&outp[(row + 1) * 64 + 4 * tx] = make_float4(hi0, hi1, hi2, hi3);
    }
}

// =====================================================================
// Kernel 2: fused point-transformer. One warp per point.
// Phases A/C: lane = (q = channel-quad 0..15, sub = neighbor parity).
// Each lane handles 4 channels of one neighbor; 2 neighbors per iter.
// =====================================================================
__global__ void __launch_bounds__(128, 8) fused_pt(
    const float* __restrict__ p,   const int*   __restrict__ idx,
    const float* __restrict__ Wp1, const float* __restrict__ bp1,
    const float* __restrict__ pg,  const float* __restrict__ pb,
    const float* __restrict__ pm,  const float* __restrict__ pv,
    const float* __restrict__ Wp2, const float* __restrict__ bp2,
    const float* __restrict__ wg1, const float* __restrict__ wb1,
    const float* __restrict__ wm1, const float* __restrict__ wv1,
    const float* __restrict__ Ww1, const float* __restrict__ bw1,
    const float* __restrict__ wg2, const float* __restrict__ wb2,
    const float* __restrict__ wm2, const float* __restrict__ wv2,
    const float* __restrict__ Ww2, const float* __restrict__ bw2,
    float* __restrict__ out)
{
    // block-wide weights
    __shared__ float2 sW1p[32][8];   // sW1p[cp][o] = {Ww1[o][2cp], Ww1[o][2cp+1]}
    __shared__ float  sW2[8][8];
    __shared__ float  sbw1[8], sa2[8], sb2[8], sbw2[8];
    __shared__ float  sWp1[9], sbp1v[3], spa[3], spbv[3];
    // per-warp (per point)
    __shared__ __align__(16) float  ssw [NBW][16][66];   // w[k][c]
    __shared__ __align__(16) float4 stv4[NBW][16];       // {t0,t1,t2,bits(j)}
    __shared__ __align__(16) float  swl [NBW][16][8];    // logits -> weights

    const int tid = threadIdx.x;

    for (int i = tid; i < 512; i += 128) {
        int cp = i >> 4, rr = i & 15, o = rr >> 1, e = rr & 1;
        ((float*)sW1p)[i] = Ww1[o * 64 + 2 * cp + e];
    }
    if (tid < 64) sW2[tid >> 3][tid & 7] = Ww2[tid];
    if (tid < 8) {
        sbw1[tid] = bw1[tid];
        float a = wg2[tid] * rsqrtf(wv2[tid] + EPSV);
        sa2[tid] = a; sb2[tid] = wb2[tid] - wm2[tid] * a;
        sbw2[tid] = bw2[tid];
    }
    if (tid < 9) sWp1[tid] = Wp1[tid];
    if (tid < 3) {
        sbp1v[tid] = bp1[tid];
        float a = pg[tid] * rsqrtf(pv[tid] + EPSV);
        spa[tid] = a; spbv[tid] = pb[tid] - pm[tid] * a;
    }
    __syncthreads();

    const int w    = tid >> 5;
    const int lane = tid & 31;
    const int n    = blockIdx.x * NBW + w;
    const int q    = lane & 15;
    const int sub  = lane >> 4;
    const int c0   = 4 * q;      // channel quad owned in phases A & C

    // ---- Phase 0: neighbor t values + index, packed per neighbor ----
    if (lane < 16) {
        int j = idx[n * 16 + lane];
        float pnx = p[n * 3 + 0], pny = p[n * 3 + 1], pnz = p[n * 3 + 2];
        float prx = p[j * 3 + 0] - pnx;
        float pry = p[j * 3 + 1] - pny;
        float prz = p[j * 3 + 2] - pnz;
        float u0 = prx * sWp1[0] + pry * sWp1[1] + prz * sWp1[2] + sbp1v[0];
        float u1 = prx * sWp1[3] + pry * sWp1[4] + prz * sWp1[5] + sbp1v[1];
        float u2 = prx * sWp1[6] + pry * sWp1[7] + prz * sWp1[8] + sbp1v[2];
        float t0 = fmaxf(0.f, fmaf(u0, spa[0], spbv[0]));
        float t1 = fmaxf(0.f, fmaf(u1, spa[1], spbv[1]));
        float t2 = fmaxf(0.f, fmaf(u2, spa[2], spbv[2]));
        stv4[w][lane] = make_float4(t0, t1, t2, __int_as_float(j));
    }
    __syncwarp();

    // ---- Phase A: gather xk (LDG.128), relation + pos-enc -> ssw ----
    {
        const u64 nxqA = neg2(*(const u64*)&g_xq[n * 64 + c0]);
        const u64 nxqB = neg2(*(const u64*)&g_xq[n * 64 + c0 + 2]);
        const u64 wpA0 = pk2(Wp2[(c0+0)*3+0], Wp2[(c0+1)*3+0]);
        const u64 wpA1 = pk2(Wp2[(c0+0)*3+1], Wp2[(c0+1)*3+1]);
        const u64 wpA2 = pk2(Wp2[(c0+0)*3+2], Wp2[(c0+1)*3+2]);
        const u64 wpB0 = pk2(Wp2[(c0+2)*3+0], Wp2[(c0+3)*3+0]);
        const u64 wpB1 = pk2(Wp2[(c0+2)*3+1], Wp2[(c0+3)*3+1]);
        const u64 wpB2 = pk2(Wp2[(c0+2)*3+2], Wp2[(c0+3)*3+2]);
        const u64 bpA  = pk2(bp2[c0],     bp2[c0 + 1]);
        const u64 bpB  = pk2(bp2[c0 + 2], bp2[c0 + 3]);
        float a1v[4], b1v[4];
        #pragma unroll
        for (int e = 0; e < 4; ++e) {
            float a = wg1[c0 + e] * rsqrtf(wv1[c0 + e] + EPSV);
            a1v[e] = a; b1v[e] = wb1[c0 + e] - wm1[c0 + e] * a;
        }

        #pragma unroll
        for (int it = 0; it < 8; ++it) {
            const int kk = 2 * it + sub;
            float4 tv = stv4[w][kk];
            int j = __float_as_int(tv.w);
            u64 t0d = pk2(tv.x, tv.x), t1d = pk2(tv.y, tv.y), t2d = pk2(tv.z, tv.z);
            ulonglong2 xkp = *(const ulonglong2*)&g_xk[j * 64 + c0];  // LDG.128
            u64 peA = ffma2(wpA0, t0d, ffma2(wpA1, t1d, ffma2(wpA2, t2d, bpA)));
            u64 peB = ffma2(wpB0, t0d, ffma2(wpB1, t1d, ffma2(wpB2, t2d, bpB)));
            u64 rA  = fadd2(fadd2(xkp.x, nxqA), peA);
            u64 rB  = fadd2(fadd2(xkp.y, nxqB), peB);
            float r0, r1, r2, r3;
            upk2(rA, r0, r1); upk2(rB, r2, r3);
            float w0 = fmaxf(0.f, fmaf(r0, a1v[0], b1v[0]));
            float w1 = fmaxf(0.f, fmaf(r1, a1v[1], b1v[1]));
            float w2_ = fmaxf(0.f, fmaf(r2, a1v[2], b1v[2]));
            float w3 = fmaxf(0.f, fmaf(r3, a1v[3], b1v[3]));
            *(u64*)&ssw[w][kk][c0]     = pk2(w0, w1);
            *(u64*)&ssw[w][kk][c0 + 2] = pk2(w2_, w3);
        }
    }
    __syncwarp();

    // ---- Phase B: w @ Ww1^T (og splits channels) -> bn2/relu -> Ww2 ----
    {
        const int k  = lane & 15;
        const int og = lane >> 4;
        const float* sswk = &ssw[w][k][0];
        u64 pacc[8] = {0,0,0,0,0,0,0,0};
        #pragma unroll
        for (int cpl = 0; cpl < 16; ++cpl) {
            u64 w2 = *(const u64*)&sswk[32 * og + 2 * cpl];
            const ulonglong2* wr = (const ulonglong2*)&sW1p[og * 16 + cpl][0];
            ulonglong2 w01 = wr[0], w23 = wr[1], w45 = wr[2], w67 = wr[3];
            pacc[0] = ffma2(w2, w01.x, pacc[0]);
            pacc[1] = ffma2(w2, w01.y, pacc[1]);
            pacc[2] = ffma2(w2, w23.x, pacc[2]);
            pacc[3] = ffma2(w2, w23.y, pacc[3]);
            pacc[4] = ffma2(w2, w45.x, pacc[4]);
            pacc[5] = ffma2(w2, w45.y, pacc[5]);
            pacc[6] = ffma2(w2, w67.x, pacc[6]);
            pacc[7] = ffma2(w2, w67.y, pacc[7]);
        }
        float h[8];
        #pragma unroll
        for (int o = 0; o < 8; ++o) {
            float lo, hi; upk2(pacc[o], lo, hi);
            float s = lo + hi;
            s += __shfl_xor_sync(0xffffffffu, s, 16);   // combine channel halves
            float tot = s + sbw1[o];
            h[o] = fmaxf(0.f, fmaf(tot, sa2[o], sb2[o]));
        }
        // logits: og half computes 4 outputs
        const int ob = og * 4;
        float lg[4];
        #pragma unroll
        for (int o2 = 0; o2 < 4; ++o2) {
            float l = sbw2[ob + o2];
            #pragma unroll
            for (int m = 0; m < 8; ++m)
                l = fmaf(h[m], sW2[ob + o2][m], l);
            lg[o2] = l;
        }
        *(u64*)&swl[w][k][ob]     = pk2(lg[0], lg[1]);
        *(u64*)&swl[w][k][ob + 2] = pk2(lg[2], lg[3]);
    }
    __syncwarp();

    // ---- softmax over the 16 neighbors (lanes 0..7) ----
    if (lane < 8) {
        float vals[16];
        float mx = -1e30f;
        #pragma unroll
        for (int kk = 0; kk < 16; ++kk) { vals[kk] = swl[w][kk][lane]; mx = fmaxf(mx, vals[kk]); }
        float s = 0.f;
        #pragma unroll
        for (int kk = 0; kk < 16; ++kk) { vals[kk] = __expf(vals[kk] - mx); s += vals[kk]; }
        float inv = 1.f / s;
        #pragma unroll
        for (int kk = 0; kk < 16; ++kk) swl[w][kk][lane] = vals[kk] * inv;
    }
    __syncwarp();

    // ---- Phase C: re-gather xv (LDG.128), recompute pe, weighted sum ----
    {
        const u64 wpA0 = pk2(Wp2[(c0+0)*3+0], Wp2[(c0+1)*3+0]);
        const u64 wpA1 = pk2(Wp2[(c0+0)*3+1], Wp2[(c0+1)*3+1]);
        const u64 wpA2 = pk2(Wp2[(c0+0)*3+2], Wp2[(c0+1)*3+2]);
        const u64 wpB0 = pk2(Wp2[(c0+2)*3+0], Wp2[(c0+3)*3+0]);
        const u64 wpB1 = pk2(Wp2[(c0+2)*3+1], Wp2[(c0+3)*3+1]);
        const u64 wpB2 = pk2(Wp2[(c0+2)*3+2], Wp2[(c0+3)*3+2]);
        const u64 bpA  = pk2(bp2[c0],     bp2[c0 + 1]);
        const u64 bpB  = pk2(bp2[c0 + 2], bp2[c0 + 3]);
        const int csq  = c0 & 7;   // 0 or 4 -> aligned 16B into swl row

        u64 acc0 = 0ull, acc1 = 0ull;
        #pragma unroll
        for (int it = 0; it < 8; ++it) {
            const int kk = 2 * it + sub;
            float4 tv = stv4[w][kk];
            int j = __float_as_int(tv.w);
            u64 t0d = pk2(tv.x, tv.x), t1d = pk2(tv.y, tv.y), t2d = pk2(tv.z, tv.z);
            ulonglong2 xvp = *(const ulonglong2*)&g_xv[j * 64 + c0];  // LDG.128
            u64 peA = ffma2(wpA0, t0d, ffma2(wpA1, t1d, ffma2(wpA2, t2d, bpA)));
            u64 peB = ffma2(wpB0, t0d, ffma2(wpB1, t1d, ffma2(wpB2, t2d, bpB)));
            ulonglong2 g2 = *(const ulonglong2*)&swl[w][kk][csq];     // LDS.128
            acc0 = ffma2(fadd2(xvp.x, peA), g2.x, acc0);
            acc1 = ffma2(fadd2(xvp.y, peB), g2.y, acc1);
        }
        float o0, o1, o2, o3;
        upk2(acc0, o0, o1); upk2(acc1, o2, o3);
        o0 += __shfl_xor_sync(0xffffffffu, o0, 16);
        o1 += __shfl_xor_sync(0xffffffffu, o1, 16);
        o2 += __shfl_xor_sync(0xffffffffu, o2, 16);
        o3 += __shfl_xor_sync(0xffffffffu, o3, 16);
        if (sub == 0)
            *(float4*)&out[n * 64 + c0] = make_float4(o0, o1, o2, o3);
    }
}

// =====================================================================
extern "C" void kernel_launch(void* const* d_in, const int* in_sizes, int n_in,
                              void* d_out, int out_size)
{
    const float* p   = (const float*)d_in[0];
    const float* x   = (const float*)d_in[1];
    const int*   idx = (const int*)  d_in[2];
    const float* Wq  = (const float*)d_in[3];
    const float* bq  = (const float*)d_in[4];
    const float* Wk  = (const float*)d_in[5];
    const float* bk  = (const float*)d_in[6];
    const float* Wv  = (const float*)d_in[7];
    const float* bv  = (const float*)d_in[8];
    const float* Wp1 = (const float*)d_in[9];
    const float* bp1 = (const float*)d_in[10];
    const float* pg  = (const float*)d_in[11];
    const float* pb  = (const float*)d_in[12];
    const float* pm  = (const float*)d_in[13];
    const float* pv  = (const float*)d_in[14];
    const float* Wp2 = (const float*)d_in[15];
    const float* bp2 = (const float*)d_in[16];
    const float* wg1 = (const float*)d_in[17];
    const float* wb1 = (const float*)d_in[18];
    const float* wm1 = (const float*)d_in[19];
    const float* wv1 = (const float*)d_in[20];
    const float* Ww1 = (const float*)d_in[21];
    const float* bw1 = (const float*)d_in[22];
    const float* wg2 = (const float*)d_in[23];
    const float* wb2 = (const float*)d_in[24];
    const float* wm2 = (const float*)d_in[25];
    const float* wv2 = (const float*)d_in[26];
    const float* Ww2 = (const float*)d_in[27];
    const float* bw2 = (const float*)d_in[28];
    float* out = (float*)d_out;

    gemm_qkv<<<dim3(NPTS / 64, 3, 1), 256>>>(x, Wq, bq, Wk, bk, Wv, bv);
    fused_pt<<<NPTS / NBW, 128>>>(p, idx, Wp1, bp1, pg, pb, pm, pv, Wp2, bp2,
                                  wg1, wb1, wm1, wv1, Ww1, bw1,
                                  wg2, wb2, wm2, wv2, Ww2, bw2, out);
}

// round 5
// speedup vs baseline: 1.3656x; 1.1760x over previous
#include <cuda_runtime.h>
#include <cuda_bf16.h>
#include <cuda_fp16.h>

typedef unsigned long long u64;
typedef unsigned int u32;

#define NPTS   65536
#define CCH    64
#define NSMP   16
#define CSW    8
#define EPSV   1e-5f
#define NBW    4   // points (warps) per block in fused kernel

// ---------------- f32x2 helpers ----------------
__device__ __forceinline__ u64 pk2(float a, float b) {
    u64 r; asm("mov.b64 %0, {%1, %2};" : "=l"(r) : "f"(a), "f"(b)); return r;
}
__device__ __forceinline__ void upk2(u64 v, float& a, float& b) {
    asm("mov.b64 {%0, %1}, %2;" : "=f"(a), "=f"(b) : "l"(v));
}
__device__ __forceinline__ u64 ffma2(u64 a, u64 b, u64 c) {
    u64 d; asm("fma.rn.f32x2 %0, %1, %2, %3;" : "=l"(d) : "l"(a), "l"(b), "l"(c)); return d;
}
__device__ __forceinline__ u64 fadd2(u64 a, u64 b) {
    u64 d; asm("add.rn.f32x2 %0, %1, %2;" : "=l"(d) : "l"(a), "l"(b)); return d;
}
__device__ __forceinline__ u64 neg2(u64 v) { return v ^ 0x8000000080000000ULL; }
__device__ __forceinline__ u32 f22h(float a, float b) {
    __half2 h = __floats2half2_rn(a, b);
    return *reinterpret_cast<u32*>(&h);
}
__device__ __forceinline__ u32 smem_u32(const void* p) {
    return (u32)__cvta_generic_to_shared(p);
}

// ---------------- scratch tables (L2-resident: 3 x 16MB) ----------------
__device__ float g_xq[NPTS * CCH];
__device__ float g_xk[NPTS * CCH];
__device__ float g_xv[NPTS * CCH];

// =====================================================================
// Kernel 1: xq/xk/xv = x @ W^T + b  (256-thread version, known good)
// =====================================================================
__global__ __launch_bounds__(256) void gemm_qkv(
    const float* __restrict__ x,
    const float* __restrict__ Wq, const float* __restrict__ bq,
    const float* __restrict__ Wk, const float* __restrict__ bk,
    const float* __restrict__ Wv, const float* __restrict__ bv)
{
    __shared__ float sX[64][68];
    __shared__ float sW[64][68];
    __shared__ float sB[64];

    const int tid = threadIdx.x;
    const int mat = blockIdx.y;
    const float* W = (mat == 0) ? Wq : (mat == 1) ? Wk : Wv;
    const float* B = (mat == 0) ? bq : (mat == 1) ? bk : bv;
    float* outp    = (mat == 0) ? g_xq : (mat == 1) ? g_xk : g_xv;
    const int row0 = blockIdx.x * 64;

    const int r  = tid & 63;
    const int kb = (tid >> 6) << 4;
    #pragma unroll
    for (int e = 0; e < 4; ++e) {
        float4 vx = *(const float4*)&x[(row0 + r) * 64 + kb + 4 * e];
        sX[kb + 4 * e + 0][r] = vx.x; sX[kb + 4 * e + 1][r] = vx.y;
        sX[kb + 4 * e + 2][r] = vx.z; sX[kb + 4 * e + 3][r] = vx.w;
        float4 vw = *(const float4*)&W[r * 64 + kb + 4 * e];
        sW[kb + 4 * e + 0][r] = vw.x; sW[kb + 4 * e + 1][r] = vw.y;
        sW[kb + 4 * e + 2][r] = vw.z; sW[kb + 4 * e + 3][r] = vw.w;
    }
    if (tid < 64) sB[tid] = B[tid];
    __syncthreads();

    const int tx = tid & 15;
    const int ty = tid >> 4;

    u64 acc[2][4];
    #pragma unroll
    for (int c = 0; c < 4; ++c) {
        float bb = sB[4 * tx + c];
        u64 bd = pk2(bb, bb);
        acc[0][c] = bd; acc[1][c] = bd;
    }

    #pragma unroll
    for (int k = 0; k < 64; ++k) {
        u64 a0 = *(const u64*)&sX[k][4 * ty];
        u64 a1 = *(const u64*)&sX[k][4 * ty + 2];
        float4 b4 = *(const float4*)&sW[k][4 * tx];
        u64 b0 = pk2(b4.x, b4.x), b1 = pk2(b4.y, b4.y);
        u64 b2 = pk2(b4.z, b4.z), b3 = pk2(b4.w, b4.w);
        acc[0][0] = ffma2(a0, b0, acc[0][0]);  acc[1][0] = ffma2(a1, b0, acc[1][0]);
        acc[0][1] = ffma2(a0, b1, acc[0][1]);  acc[1][1] = ffma2(a1, b1, acc[1][1]);
        acc[0][2] = ffma2(a0, b2, acc[0][2]);  acc[1][2] = ffma2(a1, b2, acc[1][2]);
        acc[0][3] = ffma2(a0, b3, acc[0][3]);  acc[1][3] = ffma2(a1, b3, acc[1][3]);
    }

    #pragma unroll
    for (int rp = 0; rp < 2; ++rp) {
        float lo0, hi0, lo1, hi1, lo2, hi2, lo3, hi3;
        upk2(acc[rp][0], lo0, hi0); upk2(acc[rp][1], lo1, hi1);
        upk2(acc[rp][2], lo2, hi2); upk2(acc[rp][3], lo3, hi3);
        const int row = row0 + 4 * ty + 2 * rp;
        *(float4*)&outp[(row + 0) * 64 + 4 * tx] = make_float4(lo0, lo1, lo2, lo3);
        *(float4*)&outp[(row + 1) * 64 + 4 * tx] = make_float4(hi0, hi1, hi2, hi3);
    }
}

// =====================================================================
// Kernel 2: fused point-transformer. One warp per point.
//   Phase A: lane (q,sub); fp32 gather xk; w = relu(bn1(xk-xq+pe)) -> fp16 smem
//   Phase B: ldmatrix + mma.m16n8k16 (w @ Ww1^T), bn2/relu,
//            mma.m16n8k8 (-> logits), in-register softmax over neighbors
//   Phase C: fp32 gather xv, recompute pe, weighted sum -> out
// =====================================================================
__global__ void __launch_bounds__(128, 8) fused_pt(
    const float* __restrict__ p,   const int*   __restrict__ idx,
    const float* __restrict__ Wp1, const float* __restrict__ bp1,
    const float* __restrict__ pg,  const float* __restrict__ pb,
    const float* __restrict__ pm,  const float* __restrict__ pv,
    const float* __restrict__ Wp2, const float* __restrict__ bp2,
    const float* __restrict__ wg1, const float* __restrict__ wb1,
    const float* __restrict__ wm1, const float* __restrict__ wv1,
    const float* __restrict__ Ww1, const float* __restrict__ bw1,
    const float* __restrict__ wg2, const float* __restrict__ wb2,
    const float* __restrict__ wm2, const float* __restrict__ wv2,
    const float* __restrict__ Ww2, const float* __restrict__ bw2,
    float* __restrict__ out)
{
    __shared__ float  sWp1[9], sbp1v[3], spa[3], spbv[3];
    // per-warp (per point)
    __shared__ __align__(16) __half  ssw16[NBW][16][72];  // w[k][c] fp16, row 144B
    __shared__ __align__(16) float4  stv4 [NBW][16];      // {t0,t1,t2,bits(j)}
    __shared__ __align__(16) float   swl  [NBW][16][8];   // softmax weights

    const int tid = threadIdx.x;
    if (tid < 9) sWp1[tid] = Wp1[tid];
    if (tid < 3) {
        sbp1v[tid] = bp1[tid];
        float a = pg[tid] * rsqrtf(pv[tid] + EPSV);
        spa[tid] = a; spbv[tid] = pb[tid] - pm[tid] * a;
    }
    __syncthreads();

    const int w    = tid >> 5;
    const int lane = tid & 31;
    const int n    = blockIdx.x * NBW + w;
    const int q    = lane & 15;
    const int sub  = lane >> 4;
    const int c0   = 4 * q;      // channel quad owned in phases A & C

    // ---- Phase 0: neighbor t values + index, packed per neighbor ----
    if (lane < 16) {
        int j = idx[n * 16 + lane];
        float pnx = p[n * 3 + 0], pny = p[n * 3 + 1], pnz = p[n * 3 + 2];
        float prx = p[j * 3 + 0] - pnx;
        float pry = p[j * 3 + 1] - pny;
        float prz = p[j * 3 + 2] - pnz;
        float u0 = prx * sWp1[0] + pry * sWp1[1] + prz * sWp1[2] + sbp1v[0];
        float u1 = prx * sWp1[3] + pry * sWp1[4] + prz * sWp1[5] + sbp1v[1];
        float u2 = prx * sWp1[6] + pry * sWp1[7] + prz * sWp1[8] + sbp1v[2];
        float t0 = fmaxf(0.f, fmaf(u0, spa[0], spbv[0]));
        float t1 = fmaxf(0.f, fmaf(u1, spa[1], spbv[1]));
        float t2 = fmaxf(0.f, fmaf(u2, spa[2], spbv[2]));
        stv4[w][lane] = make_float4(t0, t1, t2, __int_as_float(j));
    }
    __syncwarp();

    // ---- Phase A: gather xk (LDG.128), relation + pos-enc -> ssw16 (fp16) ----
    {
        const u64 nxqA = neg2(*(const u64*)&g_xq[n * 64 + c0]);
        const u64 nxqB = neg2(*(const u64*)&g_xq[n * 64 + c0 + 2]);
        const u64 wpA0 = pk2(Wp2[(c0+0)*3+0], Wp2[(c0+1)*3+0]);
        const u64 wpA1 = pk2(Wp2[(c0+0)*3+1], Wp2[(c0+1)*3+1]);
        const u64 wpA2 = pk2(Wp2[(c0+0)*3+2], Wp2[(c0+1)*3+2]);
        const u64 wpB0 = pk2(Wp2[(c0+2)*3+0], Wp2[(c0+3)*3+0]);
        const u64 wpB1 = pk2(Wp2[(c0+2)*3+1], Wp2[(c0+3)*3+1]);
        const u64 wpB2 = pk2(Wp2[(c0+2)*3+2], Wp2[(c0+3)*3+2]);
        const u64 bpA  = pk2(bp2[c0],     bp2[c0 + 1]);
        const u64 bpB  = pk2(bp2[c0 + 2], bp2[c0 + 3]);
        float a1v[4], b1v[4];
        #pragma unroll
        for (int e = 0; e < 4; ++e) {
            float a = wg1[c0 + e] * rsqrtf(wv1[c0 + e] + EPSV);
            a1v[e] = a; b1v[e] = wb1[c0 + e] - wm1[c0 + e] * a;
        }

        #pragma unroll
        for (int it = 0; it < 8; ++it) {
            const int kk = 2 * it + sub;
            float4 tv = stv4[w][kk];
            int j = __float_as_int(tv.w);
            u64 t0d = pk2(tv.x, tv.x), t1d = pk2(tv.y, tv.y), t2d = pk2(tv.z, tv.z);
            ulonglong2 xkp = *(const ulonglong2*)&g_xk[j * 64 + c0];  // LDG.128
            u64 peA = ffma2(wpA0, t0d, ffma2(wpA1, t1d, ffma2(wpA2, t2d, bpA)));
            u64 peB = ffma2(wpB0, t0d, ffma2(wpB1, t1d, ffma2(wpB2, t2d, bpB)));
            u64 rA  = fadd2(fadd2(xkp.x, nxqA), peA);
            u64 rB  = fadd2(fadd2(xkp.y, nxqB), peB);
            float r0, r1, r2, r3;
            upk2(rA, r0, r1); upk2(rB, r2, r3);
            float w0 = fmaxf(0.f, fmaf(r0, a1v[0], b1v[0]));
            float w1 = fmaxf(0.f, fmaf(r1, a1v[1], b1v[1]));
            float w2_ = fmaxf(0.f, fmaf(r2, a1v[2], b1v[2]));
            float w3 = fmaxf(0.f, fmaf(r3, a1v[3], b1v[3]));
            u32 hlo = f22h(w0, w1), hhi = f22h(w2_, w3);
            *(u64*)&ssw16[w][kk][c0] = (u64)hlo | ((u64)hhi << 32);  // STS.64
        }
    }
    __syncwarp();

    // ---- Phase B: mma (w @ Ww1^T) -> bn2/relu -> mma (Ww2) -> softmax ----
    {
        const int nfr = lane >> 2;       // 0..7
        const int kfr = 2 * (lane & 3);  // 0,2,4,6

        // one-shot B-fragment + constant preloads (per warp = per point)
        u32 bf[4][2];
        #pragma unroll
        for (int ch = 0; ch < 4; ++ch) {
            const float* wr = &Ww1[nfr * 64 + ch * 16 + kfr];
            bf[ch][0] = f22h(wr[0], wr[1]);
            bf[ch][1] = f22h(wr[8], wr[9]);
        }
        const u32 bW2f = f22h(Ww2[nfr * 8 + kfr], Ww2[nfr * 8 + kfr + 1]);
        const float cbw1A = bw1[kfr],     cbw1B = bw1[kfr + 1];
        float tA = wg2[kfr]     * rsqrtf(wv2[kfr]     + EPSV);
        float tB = wg2[kfr + 1] * rsqrtf(wv2[kfr + 1] + EPSV);
        const float ca2A = tA, cb2A = wb2[kfr]     - wm2[kfr]     * tA;
        const float ca2B = tB, cb2B = wb2[kfr + 1] - wm2[kfr + 1] * tB;
        const float cbw2A = bw2[kfr], cbw2B = bw2[kfr + 1];

        // ldmatrix A fragments of w (16x64 fp16)
        u32 afr[4][4];
        const int arow = lane & 15;
        const int acol = (lane >> 4) << 3;
        #pragma unroll
        for (int ch = 0; ch < 4; ++ch) {
            u32 ad = smem_u32(&ssw16[w][arow][ch * 16 + acol]);
            asm volatile("ldmatrix.sync.aligned.m8n8.x4.shared.b16 {%0,%1,%2,%3}, [%4];"
                : "=r"(afr[ch][0]), "=r"(afr[ch][1]), "=r"(afr[ch][2]), "=r"(afr[ch][3])
                : "r"(ad));
        }
        float d0 = 0.f, d1 = 0.f, d2 = 0.f, d3 = 0.f;
        #pragma unroll
        for (int ch = 0; ch < 4; ++ch) {
            asm volatile("mma.sync.aligned.m16n8k16.row.col.f32.f16.f16.f32 "
                "{%0,%1,%2,%3}, {%4,%5,%6,%7}, {%8,%9}, {%0,%1,%2,%3};"
                : "+f"(d0), "+f"(d1), "+f"(d2), "+f"(d3)
                : "r"(afr[ch][0]), "r"(afr[ch][1]), "r"(afr[ch][2]), "r"(afr[ch][3]),
                  "r"(bf[ch][0]), "r"(bf[ch][1]));
        }
        // bn2 + relu  (d0,d2 are column kfr; d1,d3 column kfr+1)
        float h0 = fmaxf(0.f, fmaf(d0 + cbw1A, ca2A, cb2A));
        float h1 = fmaxf(0.f, fmaf(d1 + cbw1B, ca2B, cb2B));
        float h2 = fmaxf(0.f, fmaf(d2 + cbw1A, ca2A, cb2A));
        float h3 = fmaxf(0.f, fmaf(d3 + cbw1B, ca2B, cb2B));
        // logits = h @ Ww2^T via m16n8k8
        u32 ha0 = f22h(h0, h1), ha1 = f22h(h2, h3);
        float l0 = 0.f, l1 = 0.f, l2 = 0.f, l3 = 0.f;
        asm volatile("mma.sync.aligned.m16n8k8.row.col.f32.f16.f16.f32 "
            "{%0,%1,%2,%3}, {%4,%5}, {%6}, {%0,%1,%2,%3};"
            : "+f"(l0), "+f"(l1), "+f"(l2), "+f"(l3)
            : "r"(ha0), "r"(ha1), "r"(bW2f));
        l0 += cbw2A; l1 += cbw2B; l2 += cbw2A; l3 += cbw2B;

        // softmax over the 16 neighbors (rows nfr and nfr+8, spread on lane>>2)
        float mA = fmaxf(l0, l2), mB = fmaxf(l1, l3);
        #pragma unroll
        for (int dlt = 4; dlt <= 16; dlt <<= 1) {
            mA = fmaxf(mA, __shfl_xor_sync(0xffffffffu, mA, dlt));
            mB = fmaxf(mB, __shfl_xor_sync(0xffffffffu, mB, dlt));
        }
        float e0 = __expf(l0 - mA), e1 = __expf(l1 - mB);
        float e2 = __expf(l2 - mA), e3 = __expf(l3 - mB);
        float sA = e0 + e2, sB = e1 + e3;
        #pragma unroll
        for (int dlt = 4; dlt <= 16; dlt <<= 1) {
            sA += __shfl_xor_sync(0xffffffffu, sA, dlt);
            sB += __shfl_xor_sync(0xffffffffu, sB, dlt);
        }
        float iA = 1.f / sA, iB = 1.f / sB;
        *(u64*)&swl[w][nfr][kfr]     = pk2(e0 * iA, e1 * iB);
        *(u64*)&swl[w][nfr + 8][kfr] = pk2(e2 * iA, e3 * iB);
    }
    __syncwarp();

    // ---- Phase C: re-gather xv (LDG.128), recompute pe, weighted sum ----
    {
        const u64 wpA0 = pk2(Wp2[(c0+0)*3+0], Wp2[(c0+1)*3+0]);
        const u64 wpA1 = pk2(Wp2[(c0+0)*3+1], Wp2[(c0+1)*3+1]);
        const u64 wpA2 = pk2(Wp2[(c0+0)*3+2], Wp2[(c0+1)*3+2]);
        const u64 wpB0 = pk2(Wp2[(c0+2)*3+0], Wp2[(c0+3)*3+0]);
        const u64 wpB1 = pk2(Wp2[(c0+2)*3+1], Wp2[(c0+3)*3+1]);
        const u64 wpB2 = pk2(Wp2[(c0+2)*3+2], Wp2[(c0+3)*3+2]);
        const u64 bpA  = pk2(bp2[c0],     bp2[c0 + 1]);
        const u64 bpB  = pk2(bp2[c0 + 2], bp2[c0 + 3]);
        const int csq  = c0 & 7;   // 0 or 4 -> aligned 16B into swl row

        u64 acc0 = 0ull, acc1 = 0ull;
        #pragma unroll
        for (int it = 0; it < 8; ++it) {
            const int kk = 2 * it + sub;
            float4 tv = stv4[w][kk];
            int j = __float_as_int(tv.w);
            u64 t0d = pk2(tv.x, tv.x), t1d = pk2(tv.y, tv.y), t2d = pk2(tv.z, tv.z);
            ulonglong2 xvp = *(const ulonglong2*)&g_xv[j * 64 + c0];  // LDG.128
            u64 peA = ffma2(wpA0, t0d, ffma2(wpA1, t1d, ffma2(wpA2, t2d, bpA)));
            u64 peB = ffma2(wpB0, t0d, ffma2(wpB1, t1d, ffma2(wpB2, t2d, bpB)));
            ulonglong2 g2 = *(const ulonglong2*)&swl[w][kk][csq];     // LDS.128
            acc0 = ffma2(fadd2(xvp.x, peA), g2.x, acc0);
            acc1 = ffma2(fadd2(xvp.y, peB), g2.y, acc1);
        }
        float o0, o1, o2, o3;
        upk2(acc0, o0, o1); upk2(acc1, o2, o3);
        o0 += __shfl_xor_sync(0xffffffffu, o0, 16);
        o1 += __shfl_xor_sync(0xffffffffu, o1, 16);
        o2 += __shfl_xor_sync(0xffffffffu, o2, 16);
        o3 += __shfl_xor_sync(0xffffffffu, o3, 16);
        if (sub == 0)
            *(float4*)&out[n * 64 + c0] = make_float4(o0, o1, o2, o3);
    }
}

// =====================================================================
extern "C" void kernel_launch(void* const* d_in, const int* in_sizes, int n_in,
                              void* d_out, int out_size)
{
    const float* p   = (const float*)d_in[0];
    const float* x   = (const float*)d_in[1];
    const int*   idx = (const int*)  d_in[2];
    const float* Wq  = (const float*)d_in[3];
    const float* bq  = (const float*)d_in[4];
    const float* Wk  = (const float*)d_in[5];
    const float* bk  = (const float*)d_in[6];
    const float* Wv  = (const float*)d_in[7];
    const float* bv  = (const float*)d_in[8];
    const float* Wp1 = (const float*)d_in[9];
    const float* bp1 = (const float*)d_in[10];
    const float* pg  = (const float*)d_in[11];
    const float* pb  = (const float*)d_in[12];
    const float* pm  = (const float*)d_in[13];
    const float* pv  = (const float*)d_in[14];
    const float* Wp2 = (const float*)d_in[15];
    const float* bp2 = (const float*)d_in[16];
    const float* wg1 = (const float*)d_in[17];
    const float* wb1 = (const float*)d_in[18];
    const float* wm1 = (const float*)d_in[19];
    const float* wv1 = (const float*)d_in[20];
    const float* Ww1 = (const float*)d_in[21];
    const float* bw1 = (const float*)d_in[22];
    const float* wg2 = (const float*)d_in[23];
    const float* wb2 = (const float*)d_in[24];
    const float* wm2 = (const float*)d_in[25];
    const float* wv2 = (const float*)d_in[26];
    const float* Ww2 = (const float*)d_in[27];
    const float* bw2 = (const float*)d_in[28];
    float* out = (float*)d_out;

    gemm_qkv<<<dim3(NPTS / 64, 3, 1), 256>>>(x, Wq, bq, Wk, bk, Wv, bv);
    fused_pt<<<NPTS / NBW, 128>>>(p, idx, Wp1, bp1, pg, pb, pm, pv, Wp2, bp2,
                                  wg1, wb1, wm1, wv1, Ww1, bw1,
                                  wg2, wb2, wm2, wv2, Ww2, bw2, out);
}